// round 2
// baseline (speedup 1.0000x reference)
#include <cuda_runtime.h>
#include <cuda_bf16.h>
#include <cstdint>

// Problem constants
#define TT  256
#define BBATCH 2048
#define DIN 128
#define NQ  16
#define GN  64          // 4 gates * NQ
#define DTOT 144        // DIN + NQ

// 134 MB scratch for zx = x @ Wx^T + b + theta   (layout: [T*B, 64])
__device__ float g_zx[(size_t)TT * BBATCH * GN];

// ---------------------------------------------------------------------------
// Helpers
// ---------------------------------------------------------------------------
__device__ __forceinline__ void split2(float x0, float x1, uint32_t& hi, uint32_t& lo) {
    __nv_bfloat16 h0 = __float2bfloat16(x0);
    __nv_bfloat16 h1 = __float2bfloat16(x1);
    float l0 = x0 - __bfloat162float(h0);
    float l1 = x1 - __bfloat162float(h1);
    __nv_bfloat16 g0 = __float2bfloat16(l0);
    __nv_bfloat16 g1 = __float2bfloat16(l1);
    hi = (uint32_t)__bfloat16_as_ushort(h0) | ((uint32_t)__bfloat16_as_ushort(h1) << 16);
    lo = (uint32_t)__bfloat16_as_ushort(g0) | ((uint32_t)__bfloat16_as_ushort(g1) << 16);
}

#define MMA_BF16(d, a, b0, b1)                                                   \
    asm volatile("mma.sync.aligned.m16n8k16.row.col.f32.bf16.bf16.f32 "          \
                 "{%0,%1,%2,%3},{%4,%5,%6,%7},{%8,%9},{%0,%1,%2,%3};\n"          \
                 : "+f"(d[0]), "+f"(d[1]), "+f"(d[2]), "+f"(d[3])                \
                 : "r"(a[0]), "r"(a[1]), "r"(a[2]), "r"(a[3]), "r"(b0), "r"(b1))

__device__ __forceinline__ float fsig(float x) {
    return __fdividef(1.0f, 1.0f + __expf(-x));
}
__device__ __forceinline__ float ftanh(float x) {
    float e = __expf(2.0f * x);               // overflow -> inf -> result 1, underflow -> -1 : both correct
    return 1.0f - __fdividef(2.0f, e + 1.0f);
}

// ---------------------------------------------------------------------------
// Phase 1: zx[t*B+b, gn] = sum_d x[t,b,d] * W[gn,d]  + bias[gn] + theta[gn]
// bf16 split-precision tensor-core GEMM: M=524288, N=64, K=128.
// Block: 256 thr (8 warps), each warp a 16-row x 64-col tile => 128 rows/block.
// ---------------------------------------------------------------------------
__global__ __launch_bounds__(256) void k_gemm(const float* __restrict__ X,
                                              const float* __restrict__ W,
                                              const float* __restrict__ bias,
                                              const float* __restrict__ theta) {
    constexpr int WS = 136;  // padded bf16 row stride (conflict-free: 68 words, 4n+q banks)
    __shared__ __nv_bfloat16 sWhi[GN * WS];
    __shared__ __nv_bfloat16 sWlo[GN * WS];
    __shared__ float sBT[GN];

    int tid = threadIdx.x;
    for (int i = tid; i < GN * DIN; i += 256) {
        int r = i >> 7;          // gn
        int c = i & 127;         // k
        float w = W[r * DTOT + c];
        __nv_bfloat16 h = __float2bfloat16(w);
        sWhi[r * WS + c] = h;
        sWlo[r * WS + c] = __float2bfloat16(w - __bfloat162float(h));
    }
    if (tid < GN) sBT[tid] = bias[tid] + theta[tid];
    __syncthreads();

    int warp = tid >> 5;
    int lane = tid & 31;
    int r0   = blockIdx.x * 128 + warp * 16 + (lane >> 2);  // rows r0 and r0+8
    int qq   = (lane & 3) * 2;
    int npos = lane >> 2;

    const float* x0 = X + (size_t)r0 * DIN;
    const float* x1 = x0 + 8 * DIN;

    float acc[8][4];
#pragma unroll
    for (int j = 0; j < 8; j++)
#pragma unroll
        for (int k = 0; k < 4; k++) acc[j][k] = 0.0f;

#pragma unroll
    for (int kc = 0; kc < 8; kc++) {
        int kb = kc * 16 + qq;
        float2 v00 = *(const float2*)(x0 + kb);
        float2 v10 = *(const float2*)(x1 + kb);
        float2 v01 = *(const float2*)(x0 + kb + 8);
        float2 v11 = *(const float2*)(x1 + kb + 8);
        uint32_t ah[4], al[4];
        split2(v00.x, v00.y, ah[0], al[0]);
        split2(v10.x, v10.y, ah[1], al[1]);
        split2(v01.x, v01.y, ah[2], al[2]);
        split2(v11.x, v11.y, ah[3], al[3]);

#pragma unroll
        for (int j = 0; j < 8; j++) {
            int nn = j * 8 + npos;
            const __nv_bfloat16* ph = sWhi + nn * WS + kb;
            const __nv_bfloat16* pl = sWlo + nn * WS + kb;
            uint32_t bh0 = *(const uint32_t*)ph;
            uint32_t bh1 = *(const uint32_t*)(ph + 8);
            uint32_t bl0 = *(const uint32_t*)pl;
            uint32_t bl1 = *(const uint32_t*)(pl + 8);
            MMA_BF16(acc[j], ah, bh0, bh1);   // hi*hi
            MMA_BF16(acc[j], ah, bl0, bl1);   // hi*lo
            MMA_BF16(acc[j], al, bh0, bh1);   // lo*hi   (lo*lo ~ 2^-18: dropped)
        }
    }

    float* out0 = g_zx + (size_t)r0 * GN;
    float* out1 = g_zx + (size_t)(r0 + 8) * GN;
#pragma unroll
    for (int j = 0; j < 8; j++) {
        int col = j * 8 + qq;
        float bt0 = sBT[col], bt1 = sBT[col + 1];
        float2 s0 = make_float2(acc[j][0] + bt0, acc[j][1] + bt1);
        float2 s1 = make_float2(acc[j][2] + bt0, acc[j][3] + bt1);
        *(float2*)(out0 + col) = s0;
        *(float2*)(out1 + col) = s1;
    }
}

// ---------------------------------------------------------------------------
// Phase 2: per-batch-element LSTM scan. 16 lanes per batch element.
// lane n owns gate outputs (g, n) for g=0..3, state h[n], c[n].
// Wh (4x16 per lane) lives in registers.  h broadcast + cumprod via shuffles.
// ---------------------------------------------------------------------------
__global__ __launch_bounds__(128) void k_scan(const float* __restrict__ W,
                                              float* __restrict__ out) {
    int lane16 = threadIdx.x & 15;
    int grp    = threadIdx.x >> 4;
    int bb     = blockIdx.x * 8 + grp;
    int n      = lane16;

    float wr[4][16];
#pragma unroll
    for (int g = 0; g < 4; g++)
#pragma unroll
        for (int j = 0; j < 16; j++)
            wr[g][j] = W[(g * 16 + n) * DTOT + DIN + j];

    float h = 0.0f, c = 0.0f;
    const float* zb = g_zx + (size_t)bb * GN;
    float* op = out + (size_t)bb * NQ + n;

    for (int t = 0; t < TT; t++) {
        const float* z = zb + (size_t)t * BBATCH * GN;
        float z0 = z[n], z1 = z[16 + n], z2 = z[32 + n], z3 = z[48 + n];

#pragma unroll
        for (int j = 0; j < 16; j++) {
            float hj = __shfl_sync(0xffffffffu, h, j, 16);
            z0 = fmaf(hj, wr[0][j], z0);
            z1 = fmaf(hj, wr[1][j], z1);
            z2 = fmaf(hj, wr[2][j], z2);
            z3 = fmaf(hj, wr[3][j], z3);
        }

        float a0 = __cosf(z0), a1 = __cosf(z1), a2 = __cosf(z2), a3 = __cosf(z3);

        // inclusive cumprod over the 16 lanes (log-step scan)
#pragma unroll
        for (int off = 1; off < 16; off <<= 1) {
            float p0 = __shfl_up_sync(0xffffffffu, a0, off, 16);
            float p1 = __shfl_up_sync(0xffffffffu, a1, off, 16);
            float p2 = __shfl_up_sync(0xffffffffu, a2, off, 16);
            float p3 = __shfl_up_sync(0xffffffffu, a3, off, 16);
            if (lane16 >= off) { a0 *= p0; a1 *= p1; a2 *= p2; a3 *= p3; }
        }

        float f  = fsig(a0);
        float i  = fsig(a1);
        float gg = ftanh(a2);
        float o  = fsig(a3);
        c = f * c + i * gg;
        h = o * ftanh(c);

        op[(size_t)t * BBATCH * NQ] = h;
    }

    // final hx, cx appended after outputs
    size_t base = (size_t)TT * BBATCH * NQ;
    out[base + (size_t)bb * NQ + n]                         = h;
    out[base + (size_t)BBATCH * NQ + (size_t)bb * NQ + n]   = c;
}

// ---------------------------------------------------------------------------
extern "C" void kernel_launch(void* const* d_in, const int* in_sizes, int n_in,
                              void* d_out, int out_size) {
    const float* X     = (const float*)d_in[0];  // [T, B, DIN]
    const float* W     = (const float*)d_in[1];  // [4, NQ, DIN+NQ]
    const float* bias  = (const float*)d_in[2];  // [4, NQ]
    const float* theta = (const float*)d_in[3];  // [4, NQ]
    float* out = (float*)d_out;

    // Phase 1: 524288 rows / 128 rows per block
    k_gemm<<<(TT * BBATCH) / 128, 256>>>(X, W, bias, theta);
    // Phase 2: 2048 batch elements / 8 per block
    k_scan<<<BBATCH / 8, 128>>>(W, out);
}

// round 3
// speedup vs baseline: 1.2100x; 1.2100x over previous
#include <cuda_runtime.h>
#include <cuda_bf16.h>
#include <cstdint>

// Problem constants
#define TT  256
#define BBATCH 2048
#define DIN 128
#define NQ  16
#define GN  64          // 4 gates * NQ
#define DTOT 144        // DIN + NQ

// 134 MB scratch for zx = x @ Wx^T + b + theta   (layout: [T*B, 64])
__device__ float g_zx[(size_t)TT * BBATCH * GN];

// ---------------------------------------------------------------------------
// Helpers
// ---------------------------------------------------------------------------
__device__ __forceinline__ void split2(float x0, float x1, uint32_t& hi, uint32_t& lo) {
    __nv_bfloat16 h0 = __float2bfloat16(x0);
    __nv_bfloat16 h1 = __float2bfloat16(x1);
    float l0 = x0 - __bfloat162float(h0);
    float l1 = x1 - __bfloat162float(h1);
    __nv_bfloat16 g0 = __float2bfloat16(l0);
    __nv_bfloat16 g1 = __float2bfloat16(l1);
    hi = (uint32_t)__bfloat16_as_ushort(h0) | ((uint32_t)__bfloat16_as_ushort(h1) << 16);
    lo = (uint32_t)__bfloat16_as_ushort(g0) | ((uint32_t)__bfloat16_as_ushort(g1) << 16);
}

#define MMA_BF16(d, a, b0, b1)                                                   \
    asm volatile("mma.sync.aligned.m16n8k16.row.col.f32.bf16.bf16.f32 "          \
                 "{%0,%1,%2,%3},{%4,%5,%6,%7},{%8,%9},{%0,%1,%2,%3};\n"          \
                 : "+f"(d[0]), "+f"(d[1]), "+f"(d[2]), "+f"(d[3])                \
                 : "r"(a[0]), "r"(a[1]), "r"(a[2]), "r"(a[3]), "r"(b0), "r"(b1))

// ---------------------------------------------------------------------------
// Phase 1: zx[t*B+b, gn] = sum_d x[t,b,d] * W[gn,d]  + bias[gn] + theta[gn]
// bf16 split-precision tensor-core GEMM: M=524288, N=64, K=128.
// ---------------------------------------------------------------------------
__global__ __launch_bounds__(256) void k_gemm(const float* __restrict__ X,
                                              const float* __restrict__ W,
                                              const float* __restrict__ bias,
                                              const float* __restrict__ theta) {
    constexpr int WS = 136;  // padded bf16 row stride
    __shared__ __nv_bfloat16 sWhi[GN * WS];
    __shared__ __nv_bfloat16 sWlo[GN * WS];
    __shared__ float sBT[GN];

    int tid = threadIdx.x;
    for (int i = tid; i < GN * DIN; i += 256) {
        int r = i >> 7;          // gn
        int c = i & 127;         // k
        float w = W[r * DTOT + c];
        __nv_bfloat16 h = __float2bfloat16(w);
        sWhi[r * WS + c] = h;
        sWlo[r * WS + c] = __float2bfloat16(w - __bfloat162float(h));
    }
    if (tid < GN) sBT[tid] = bias[tid] + theta[tid];
    __syncthreads();

    int warp = tid >> 5;
    int lane = tid & 31;
    int r0   = blockIdx.x * 128 + warp * 16 + (lane >> 2);  // rows r0 and r0+8
    int qq   = (lane & 3) * 2;
    int npos = lane >> 2;

    const float* x0 = X + (size_t)r0 * DIN;
    const float* x1 = x0 + 8 * DIN;

    float acc[8][4];
#pragma unroll
    for (int j = 0; j < 8; j++)
#pragma unroll
        for (int k = 0; k < 4; k++) acc[j][k] = 0.0f;

#pragma unroll
    for (int kc = 0; kc < 8; kc++) {
        int kb = kc * 16 + qq;
        float2 v00 = *(const float2*)(x0 + kb);
        float2 v10 = *(const float2*)(x1 + kb);
        float2 v01 = *(const float2*)(x0 + kb + 8);
        float2 v11 = *(const float2*)(x1 + kb + 8);
        uint32_t ah[4], al[4];
        split2(v00.x, v00.y, ah[0], al[0]);
        split2(v10.x, v10.y, ah[1], al[1]);
        split2(v01.x, v01.y, ah[2], al[2]);
        split2(v11.x, v11.y, ah[3], al[3]);

#pragma unroll
        for (int j = 0; j < 8; j++) {
            int nn = j * 8 + npos;
            const __nv_bfloat16* ph = sWhi + nn * WS + kb;
            const __nv_bfloat16* pl = sWlo + nn * WS + kb;
            uint32_t bh0 = *(const uint32_t*)ph;
            uint32_t bh1 = *(const uint32_t*)(ph + 8);
            uint32_t bl0 = *(const uint32_t*)pl;
            uint32_t bl1 = *(const uint32_t*)(pl + 8);
            MMA_BF16(acc[j], ah, bh0, bh1);   // hi*hi
            MMA_BF16(acc[j], ah, bl0, bl1);   // hi*lo
            MMA_BF16(acc[j], al, bh0, bh1);   // lo*hi
        }
    }

    float* out0 = g_zx + (size_t)r0 * GN;
    float* out1 = g_zx + (size_t)(r0 + 8) * GN;
#pragma unroll
    for (int j = 0; j < 8; j++) {
        int col = j * 8 + qq;
        float bt0 = sBT[col], bt1 = sBT[col + 1];
        float2 s0 = make_float2(acc[j][0] + bt0, acc[j][1] + bt1);
        float2 s1 = make_float2(acc[j][2] + bt0, acc[j][3] + bt1);
        *(float2*)(out0 + col) = s0;
        *(float2*)(out1 + col) = s1;
    }
}

// ---------------------------------------------------------------------------
// Phase 2: per-batch-element LSTM scan. ONE WARP per batch element.
// Lane l: n = l&15, slot A = gate (l>>4) in {0:f, 1:i},
//                   slot B = gate (l>>4)+2 in {2:g, 3:o}.
// h broadcast + cumprod + gate gathers via shuffles; z prefetched 2 steps.
// ---------------------------------------------------------------------------
__global__ __launch_bounds__(128) void k_scan(const float* __restrict__ W,
                                              float* __restrict__ out) {
    int l    = threadIdx.x & 31;
    int warp = threadIdx.x >> 5;
    int bb   = blockIdx.x * 4 + warp;
    int n    = l & 15;
    int gA   = l >> 4;                 // 0 or 1

    // Wh rows for this lane's two gate outputs
    float wrA[16], wrB[16];
#pragma unroll
    for (int j = 0; j < 16; j++) {
        wrA[j] = W[(gA * 16 + n) * DTOT + DIN + j];
        wrB[j] = W[((gA + 2) * 16 + n) * DTOT + DIN + j];
    }

    const float* zb = g_zx + (size_t)bb * GN;
    const size_t tstep = (size_t)BBATCH * GN;
    float* op = out + (size_t)bb * NQ + n;

    float h = 0.0f, c = 0.0f;

    // distance-2 prefetch pipeline
    float zA0 = __ldg(zb + l);
    float zB0 = __ldg(zb + 32 + l);
    float zA1 = __ldg(zb + tstep + l);
    float zB1 = __ldg(zb + tstep + 32 + l);

    // slot-B activation params: gate2 -> tanh(x)=2*sigma(2x)-1, gate3 -> sigma
    const float sclB = (gA == 0) ? 2.0f : 1.0f;
    const float mB   = (gA == 0) ? 2.0f : 1.0f;
    const float aB   = (gA == 0) ? -1.0f : 0.0f;

    for (int t = 0; t < TT; t++) {
        int tp = (t + 2 < TT) ? (t + 2) : (TT - 1);
        const float* zp = zb + (size_t)tp * tstep;
        float zA2 = __ldg(zp + l);
        float zB2 = __ldg(zp + 32 + l);

        // zh = Wh * h : split 16-deep chain into two 8-deep accumulators
        float aA0 = zA0, aA1 = 0.0f, aB0 = zB0, aB1 = 0.0f;
#pragma unroll
        for (int j = 0; j < 8; j++) {
            float hj = __shfl_sync(0xffffffffu, h, j, 32);
            aA0 = fmaf(hj, wrA[j], aA0);
            aB0 = fmaf(hj, wrB[j], aB0);
        }
#pragma unroll
        for (int j = 8; j < 16; j++) {
            float hj = __shfl_sync(0xffffffffu, h, j, 32);
            aA1 = fmaf(hj, wrA[j], aA1);
            aB1 = fmaf(hj, wrB[j], aB1);
        }
        float zA = aA0 + aA1;
        float zB = aB0 + aB1;

        float pA = __cosf(zA);
        float pB = __cosf(zB);

        // inclusive cumprod over the 16-lane segment (log-step scan)
#pragma unroll
        for (int off = 1; off < 16; off <<= 1) {
            float sA = __shfl_up_sync(0xffffffffu, pA, off, 16);
            float sB = __shfl_up_sync(0xffffffffu, pB, off, 16);
            if (n >= off) { pA *= sA; pB *= sB; }
        }

        // slot A: sigmoid (f on lanes<16, i on lanes>=16)
        float sigA = __fdividef(1.0f, 1.0f + __expf(-pA));
        // slot B: m*sigma(s*x)+a  (tanh on lanes<16, sigmoid on lanes>=16)
        float sB2  = __fdividef(1.0f, 1.0f + __expf(-sclB * pB));
        float valB = fmaf(mB, sB2, aB);

        // gather: lanes<16 get i and o from upper half
        float i_ = __shfl_sync(0xffffffffu, sigA, n + 16, 32);
        float o_ = __shfl_sync(0xffffffffu, valB, n + 16, 32);

        // state update (valid on lanes 0..15; upper lanes compute garbage,
        // but h is only ever shuffled from lanes 0..15)
        c = fmaf(sigA, c, i_ * valB);
        float ec  = __expf(2.0f * c);
        float thc = 1.0f - __fdividef(2.0f, ec + 1.0f);
        h = o_ * thc;

        if (l < 16) op[(size_t)t * ((size_t)BBATCH * NQ)] = h;

        zA0 = zA1; zB0 = zB1;
        zA1 = zA2; zB1 = zB2;
    }

    if (l < 16) {
        size_t base = (size_t)TT * BBATCH * NQ;
        out[base + (size_t)bb * NQ + n]                       = h;
        out[base + (size_t)BBATCH * NQ + (size_t)bb * NQ + n] = c;
    }
}

// ---------------------------------------------------------------------------
extern "C" void kernel_launch(void* const* d_in, const int* in_sizes, int n_in,
                              void* d_out, int out_size) {
    const float* X     = (const float*)d_in[0];  // [T, B, DIN]
    const float* W     = (const float*)d_in[1];  // [4, NQ, DIN+NQ]
    const float* bias  = (const float*)d_in[2];  // [4, NQ]
    const float* theta = (const float*)d_in[3];  // [4, NQ]
    float* out = (float*)d_out;

    // Phase 1: 524288 rows / 128 rows per block
    k_gemm<<<(TT * BBATCH) / 128, 256>>>(X, W, bias, theta);
    // Phase 2: one warp per batch element, 4 per block
    k_scan<<<BBATCH / 4, 128>>>(W, out);
}